// round 9
// baseline (speedup 1.0000x reference)
#include <cuda_runtime.h>
#include <cuda_fp16.h>
#include <cstdint>

#define NSEQ   1024
#define DHEAD  128
#define BM     128
#define BN     64
#define NTHR   128
#define BH_TOT 64
#define TILE_U4 1024                     // uint4 per packed K or V tile (16 KB)
// smem (uint4 units): K0[0,1024) V0[1024,2048) K1[2048,3072) V1[3072,4096) Q[4096,6144)
#define SMEM_BYTES (6144 * 16)           // 96 KB

// packed fp16 fragment-ready operands (16 MB each) + adj bitmask
__device__ uint4    g_Kp[BH_TOT * 16 * TILE_U4];
__device__ uint4    g_Vp[BH_TOT * 16 * TILE_U4];
__device__ uint32_t g_maskbits[NSEQ * (NSEQ / 32)];

__device__ __forceinline__ uint32_t h2pack(float a, float b) {
    __half2 h = __floats2half2_rn(a, b);
    return *reinterpret_cast<uint32_t*>(&h);
}

__device__ __forceinline__ void mma_f16(float c[4], const uint32_t a[4],
                                        uint32_t b0, uint32_t b1) {
    asm volatile(
        "mma.sync.aligned.m16n8k16.row.col.f32.f16.f16.f32 "
        "{%0,%1,%2,%3}, {%4,%5,%6,%7}, {%8,%9}, {%0,%1,%2,%3};"
        : "+f"(c[0]), "+f"(c[1]), "+f"(c[2]), "+f"(c[3])
        : "r"(a[0]), "r"(a[1]), "r"(a[2]), "r"(a[3]), "r"(b0), "r"(b1));
}

#define CPASYNC16(dst, src) \
    asm volatile("cp.async.cg.shared.global [%0], [%1], 16;" :: "r"(dst), "l"(src))
#define CPCOMMIT() asm volatile("cp.async.commit_group;")
#define CPWAIT1()  asm volatile("cp.async.wait_group 1;" ::: "memory")

// ===== prepass kernels (unchanged layouts) =====
__global__ void pack_mask_kernel(const int* __restrict__ adj) {
    int idx = blockIdx.x * blockDim.x + threadIdx.x;     // 0..32767
    const int4* src = (const int4*)(adj + (size_t)idx * 32);
    uint32_t m = 0;
    #pragma unroll
    for (int i = 0; i < 8; i++) {
        int4 v = src[i];
        m |= (v.x > 0 ? 1u : 0u) << (4 * i);
        m |= (v.y > 0 ? 1u : 0u) << (4 * i + 1);
        m |= (v.z > 0 ? 1u : 0u) << (4 * i + 2);
        m |= (v.w > 0 ? 1u : 0u) << (4 * i + 3);
    }
    g_maskbits[idx] = m;
}

__global__ void pack_kv_kernel(const float* __restrict__ K, const float* __restrict__ V) {
    int t = blockIdx.x * blockDim.x + threadIdx.x;       // 0..1048575
    int lane = t & 31;
    int g = lane >> 2, t4 = lane & 3;
    int kt = (t >> 10) & 15, bh = t >> 14;
    if (blockIdx.y == 0) {
        int kpp = (t >> 5) & 3, nb = (t >> 7) & 7;
        const float* src = K + ((size_t)bh * NSEQ + kt * 64 + nb * 8 + g) * DHEAD
                             + 32 * kpp + 2 * t4;
        uint4 o;
        o.x = h2pack(src[0],  src[1]);
        o.y = h2pack(src[8],  src[9]);
        o.z = h2pack(src[16], src[17]);
        o.w = h2pack(src[24], src[25]);
        g_Kp[t] = o;
    } else {
        int nd2 = (t >> 5) & 7, ks2 = (t >> 8) & 3;
        int ra = kt * 64 + 16 * ks2 + 2 * t4;
        int c0 = 16 * nd2 + g;
        const float* src = V + ((size_t)bh * NSEQ + ra) * DHEAD;
        uint4 o;
        o.x = h2pack(src[c0],                 src[DHEAD + c0]);
        o.y = h2pack(src[8 * DHEAD + c0],     src[9 * DHEAD + c0]);
        o.z = h2pack(src[c0 + 8],             src[DHEAD + c0 + 8]);
        o.w = h2pack(src[8 * DHEAD + c0 + 8], src[9 * DHEAD + c0 + 8]);
        g_Vp[t] = o;
    }
}

// ===== main kernel: 128 Q-rows per CTA, 32 rows per warp =====
__global__ __launch_bounds__(NTHR, 2)
void attn_f16_kernel(const float* __restrict__ Qg, float* __restrict__ Out) {
    extern __shared__ uint4 smem[];
    const uint32_t sbase = (uint32_t)__cvta_generic_to_shared(smem);
    uint4* sQ = smem + 4096;

    const int tid  = threadIdx.x;
    const int w    = tid >> 5;
    const int lane = tid & 31;
    const int g    = lane >> 2;
    const int t4   = lane & 3;
    const int bh   = blockIdx.y;
    const int q0   = blockIdx.x * BM;
    const size_t headoff = (size_t)bh * NSEQ * DHEAD;

    const uint4* gK = g_Kp + (size_t)bh * 16 * TILE_U4;
    const uint4* gV = g_Vp + (size_t)bh * 16 * TILE_U4;

    // ---- prefetch tile 0 into stage 0 ----
    #pragma unroll
    for (int i = 0; i < 8; i++) {
        int idx = tid + i * NTHR;
        CPASYNC16(sbase + idx * 16,         gK + idx);
        CPASYNC16(sbase + 16384 + idx * 16, gV + idx);
    }
    CPCOMMIT();

    // ---- pack Q tile into smem a-frag layout: sQ[(mt*8+ks)*32+lane] ----
    {
        #pragma unroll
        for (int i = 0; i < 16; i++) {
            int idx = tid + i * NTHR;          // 0..2047
            int mt  = idx >> 8;
            int ks  = (idx >> 5) & 7;
            int l2  = idx & 31;
            int g2  = l2 >> 2, t42 = l2 & 3;
            const float* p0 = Qg + headoff + (size_t)(q0 + mt * 16 + g2) * DHEAD
                                 + ks * 16 + 2 * t42;
            const float* p1 = p0 + 8 * DHEAD;
            float2 a = *(const float2*)(p0);
            float2 b = *(const float2*)(p1);
            float2 c = *(const float2*)(p0 + 8);
            float2 d = *(const float2*)(p1 + 8);
            uint4 o;
            o.x = h2pack(a.x, a.y);
            o.y = h2pack(b.x, b.y);
            o.z = h2pack(c.x, c.y);
            o.w = h2pack(d.x, d.y);
            sQ[idx] = o;
        }
    }

    const int mt0 = 2 * w, mt1 = 2 * w + 1;     // this warp's M-tiles
    float oacc[2][16][4];
    #pragma unroll
    for (int mt = 0; mt < 2; mt++)
        #pragma unroll
        for (int nd = 0; nd < 16; nd++) {
            oacc[mt][nd][0] = 0.f; oacc[mt][nd][1] = 0.f;
            oacc[mt][nd][2] = 0.f; oacc[mt][nd][3] = 0.f;
        }
    float lsum[2][2] = {{0.f, 0.f}, {0.f, 0.f}};

    // mask row base: warp rows = q0 + w*32 + {0,8,16,24} + g
    const uint32_t* mbase = g_maskbits + (size_t)(q0 + w * 32 + g) * 32;

    for (int kt = 0; kt < NSEQ / BN; kt++) {
        const int cur = kt & 1;

        // mask words: 4 row-groups x 2 halves (L2 hits)
        uint32_t mw[4][2];
        #pragma unroll
        for (int i = 0; i < 4; i++) {
            mw[i][0] = mbase[i * 256 + kt * 2];
            mw[i][1] = mbase[i * 256 + kt * 2 + 1];
        }

        __syncthreads();   // spare stage free + (first iter) Q pack visible

        if (kt + 1 < NSEQ / BN) {
            const uint4* nK = gK + (size_t)(kt + 1) * TILE_U4;
            const uint4* nV = gV + (size_t)(kt + 1) * TILE_U4;
            uint32_t dst = sbase + (cur ^ 1) * 32768;
            #pragma unroll
            for (int i = 0; i < 8; i++) {
                int idx = tid + i * NTHR;
                CPASYNC16(dst + idx * 16,         nK + idx);
                CPASYNC16(dst + 16384 + idx * 16, nV + idx);
            }
        }
        CPCOMMIT();
        CPWAIT1();
        __syncthreads();

        const uint4* sK = smem + cur * 2048;
        const uint4* sV = sK + 1024;

        #pragma unroll
        for (int h = 0; h < 2; h++) {
            float sacc[2][4][4];
            #pragma unroll
            for (int mt = 0; mt < 2; mt++)
                #pragma unroll
                for (int nbl = 0; nbl < 4; nbl++) {
                    sacc[mt][nbl][0] = 0.f; sacc[mt][nbl][1] = 0.f;
                    sacc[mt][nbl][2] = 0.f; sacc[mt][nbl][3] = 0.f;
                }

            #pragma unroll
            for (int kpp = 0; kpp < 4; kpp++) {
                uint4 qA0 = sQ[(mt0 * 8 + 2 * kpp)     * 32 + lane];
                uint4 qA1 = sQ[(mt0 * 8 + 2 * kpp + 1) * 32 + lane];
                uint4 qB0 = sQ[(mt1 * 8 + 2 * kpp)     * 32 + lane];
                uint4 qB1 = sQ[(mt1 * 8 + 2 * kpp + 1) * 32 + lane];
                #pragma unroll
                for (int nbl = 0; nbl < 4; nbl++) {
                    uint4 kw = sK[((h * 4 + nbl) * 4 + kpp) * 32 + lane];
                    mma_f16(sacc[0][nbl], (const uint32_t*)&qA0, kw.x, kw.y);
                    mma_f16(sacc[0][nbl], (const uint32_t*)&qA1, kw.z, kw.w);
                    mma_f16(sacc[1][nbl], (const uint32_t*)&qB0, kw.x, kw.y);
                    mma_f16(sacc[1][nbl], (const uint32_t*)&qB1, kw.z, kw.w);
                }
            }

            // mask + exp + pack P a-frags
            uint32_t pa[2][2][4];
            #pragma unroll
            for (int mt = 0; mt < 2; mt++) {
                uint32_t mr0 = mw[2 * mt][h];
                uint32_t mr1 = mw[2 * mt + 1][h];
                #pragma unroll
                for (int nbl = 0; nbl < 4; nbl++) {
                    int bi = nbl * 8 + 2 * t4;
                    float p0 = ((mr0 >> bi) & 1u)       ? __expf(sacc[mt][nbl][0] * 0.125f) : 0.f;
                    float p1 = ((mr0 >> (bi + 1)) & 1u) ? __expf(sacc[mt][nbl][1] * 0.125f) : 0.f;
                    float p2 = ((mr1 >> bi) & 1u)       ? __expf(sacc[mt][nbl][2] * 0.125f) : 0.f;
                    float p3 = ((mr1 >> (bi + 1)) & 1u) ? __expf(sacc[mt][nbl][3] * 0.125f) : 0.f;
                    lsum[mt][0] += p0 + p1;
                    lsum[mt][1] += p2 + p3;
                    int j = nbl >> 1;
                    if ((nbl & 1) == 0) {
                        pa[mt][j][0] = h2pack(p0, p1);
                        pa[mt][j][1] = h2pack(p2, p3);
                    } else {
                        pa[mt][j][2] = h2pack(p0, p1);
                        pa[mt][j][3] = h2pack(p2, p3);
                    }
                }
            }

            // O += P V  (V fragment read once, used by both M-tiles)
            #pragma unroll
            for (int j = 0; j < 2; j++) {
                int ks2 = 2 * h + j;
                #pragma unroll
                for (int nd2 = 0; nd2 < 8; nd2++) {
                    uint4 vw = sV[(ks2 * 8 + nd2) * 32 + lane];
                    mma_f16(oacc[0][2 * nd2],     pa[0][j], vw.x, vw.y);
                    mma_f16(oacc[0][2 * nd2 + 1], pa[0][j], vw.z, vw.w);
                    mma_f16(oacc[1][2 * nd2],     pa[1][j], vw.x, vw.y);
                    mma_f16(oacc[1][2 * nd2 + 1], pa[1][j], vw.z, vw.w);
                }
            }
        }
    }

    // ---- epilogue ----
    #pragma unroll
    for (int mt = 0; mt < 2; mt++) {
        float s0 = lsum[mt][0], s1 = lsum[mt][1];
        s0 += __shfl_xor_sync(0xffffffffu, s0, 1);
        s0 += __shfl_xor_sync(0xffffffffu, s0, 2);
        s1 += __shfl_xor_sync(0xffffffffu, s1, 1);
        s1 += __shfl_xor_sync(0xffffffffu, s1, 2);
        float inv0 = 1.0f / s0;
        float inv1 = 1.0f / s1;

        float* o0 = Out + headoff + (size_t)(q0 + w * 32 + 16 * mt + g) * DHEAD;
        float* o1 = o0 + 8 * DHEAD;
        #pragma unroll
        for (int nd = 0; nd < 16; nd++) {
            int c = nd * 8 + 2 * t4;
            float2 a; a.x = oacc[mt][nd][0] * inv0; a.y = oacc[mt][nd][1] * inv0;
            *(float2*)(o0 + c) = a;
            float2 b; b.x = oacc[mt][nd][2] * inv1; b.y = oacc[mt][nd][3] * inv1;
            *(float2*)(o1 + c) = b;
        }
    }
}

extern "C" void kernel_launch(void* const* d_in, const int* in_sizes, int n_in,
                              void* d_out, int out_size) {
    const float* Q   = (const float*)d_in[0];
    const float* K   = (const float*)d_in[1];
    const float* V   = (const float*)d_in[2];
    const int*   adj = (const int*)d_in[3];
    float* out = (float*)d_out;

    const int BH = in_sizes[0] / (NSEQ * DHEAD);     // 64

    pack_mask_kernel<<<NSEQ * (NSEQ / 32) / 256, 256>>>(adj);
    {
        dim3 pg((BH * 16 * TILE_U4) / 256, 2);
        pack_kv_kernel<<<pg, 256>>>(K, V);
    }

    cudaFuncSetAttribute(attn_f16_kernel,
                         cudaFuncAttributeMaxDynamicSharedMemorySize, SMEM_BYTES);

    dim3 grid(NSEQ / BM, BH);
    attn_f16_kernel<<<grid, NTHR, SMEM_BYTES>>>(Q, out);
}

// round 11
// speedup vs baseline: 1.2156x; 1.2156x over previous
#include <cuda_runtime.h>
#include <cuda_fp16.h>
#include <cstdint>

#define NSEQ   1024
#define DHEAD  128
#define BM     64
#define BN     64
#define NTHR   128
#define BH_TOT 64
#define TILE_U4 1024          // uint4 per packed tile (16 KB)
#define SMEM_BYTES (4 * TILE_U4 * 16)   // 2 stages x (K|V) = 64 KB

// packed fp16 fragment-ready operands (16 MB each) + adj bitmask
__device__ uint4    g_Kp[BH_TOT * 16 * TILE_U4];
__device__ uint4    g_Vp[BH_TOT * 16 * TILE_U4];
__device__ uint32_t g_maskbits[NSEQ * (NSEQ / 32)];

__device__ __forceinline__ uint32_t h2pack(float a, float b) {
    __half2 h = __floats2half2_rn(a, b);
    return *reinterpret_cast<uint32_t*>(&h);
}

__device__ __forceinline__ void mma_f16(float c[4], const uint32_t a[4],
                                        uint32_t b0, uint32_t b1) {
    asm volatile(
        "mma.sync.aligned.m16n8k16.row.col.f32.f16.f16.f32 "
        "{%0,%1,%2,%3}, {%4,%5,%6,%7}, {%8,%9}, {%0,%1,%2,%3};"
        : "+f"(c[0]), "+f"(c[1]), "+f"(c[2]), "+f"(c[3])
        : "r"(a[0]), "r"(a[1]), "r"(a[2]), "r"(a[3]), "r"(b0), "r"(b1));
}

#define CPASYNC16(dst, src) \
    asm volatile("cp.async.cg.shared.global [%0], [%1], 16;" :: "r"(dst), "l"(src))
#define CPCOMMIT() asm volatile("cp.async.commit_group;")
#define CPWAIT1()  asm volatile("cp.async.wait_group 1;" ::: "memory")

// ===== single fused prepass kernel =====
// blocks [0, KB)           : K fragment pack (scale 1/8 folded in)
// blocks [KB, KB+VB)       : V fragment pack
// blocks [KB+VB, +MB)      : adj bitmask pack
#define PK_KB 4096
#define PK_VB 4096
#define PK_MB 128
__global__ void prepack_kernel(const float* __restrict__ K,
                               const float* __restrict__ V,
                               const int*   __restrict__ adj) {
    int b = blockIdx.x;
    if (b < PK_KB) {
        int t = b * 256 + threadIdx.x;                 // 0..1048575
        int lane = t & 31;
        int g = lane >> 2, t4 = lane & 3;
        int kpp = (t >> 5) & 3, nb = (t >> 7) & 7;
        int kt = (t >> 10) & 15, bh = t >> 14;
        const float* src = K + ((size_t)bh * NSEQ + kt * 64 + nb * 8 + g) * DHEAD
                             + 32 * kpp + 2 * t4;
        uint4 o;
        o.x = h2pack(0.125f * src[0],  0.125f * src[1]);
        o.y = h2pack(0.125f * src[8],  0.125f * src[9]);
        o.z = h2pack(0.125f * src[16], 0.125f * src[17]);
        o.w = h2pack(0.125f * src[24], 0.125f * src[25]);
        g_Kp[t] = o;
    } else if (b < PK_KB + PK_VB) {
        int t = (b - PK_KB) * 256 + threadIdx.x;
        int lane = t & 31;
        int g = lane >> 2, t4 = lane & 3;
        int nd2 = (t >> 5) & 7, ks2 = (t >> 8) & 3;
        int kt = (t >> 10) & 15, bh = t >> 14;
        int ra = kt * 64 + 16 * ks2 + 2 * t4;
        int c0 = 16 * nd2 + g;
        const float* src = V + ((size_t)bh * NSEQ + ra) * DHEAD;
        uint4 o;
        o.x = h2pack(src[c0],                 src[DHEAD + c0]);
        o.y = h2pack(src[8 * DHEAD + c0],     src[9 * DHEAD + c0]);
        o.z = h2pack(src[c0 + 8],             src[DHEAD + c0 + 8]);
        o.w = h2pack(src[8 * DHEAD + c0 + 8], src[9 * DHEAD + c0 + 8]);
        g_Vp[t] = o;
    } else {
        int idx = (b - PK_KB - PK_VB) * 256 + threadIdx.x;   // 0..32767
        const int4* src = (const int4*)(adj + (size_t)idx * 32);
        uint32_t m = 0;
        #pragma unroll
        for (int i = 0; i < 8; i++) {
            int4 v = src[i];
            m |= (v.x > 0 ? 1u : 0u) << (4 * i);
            m |= (v.y > 0 ? 1u : 0u) << (4 * i + 1);
            m |= (v.z > 0 ? 1u : 0u) << (4 * i + 2);
            m |= (v.w > 0 ? 1u : 0u) << (4 * i + 3);
        }
        g_maskbits[idx] = m;
    }
}

// ===== main kernel (R8 structure: BM=64, 4 warps, 2-stage pipeline) =====
__global__ __launch_bounds__(NTHR, 3)
void attn_f16_kernel(const float* __restrict__ Qg, float* __restrict__ Out) {
    extern __shared__ uint4 smem[];                      // [2][2048]: stage -> K(1024)|V(1024)
    const uint32_t sbase = (uint32_t)__cvta_generic_to_shared(smem);

    const int tid  = threadIdx.x;
    const int w    = tid >> 5;
    const int lane = tid & 31;
    const int g    = lane >> 2;
    const int t4   = lane & 3;
    const int bh   = blockIdx.y;
    const int q0   = blockIdx.x * BM;
    const int rl0  = w * 16 + g;
    const int rl1  = rl0 + 8;
    const size_t headoff = (size_t)bh * NSEQ * DHEAD;

    const uint4* gK = g_Kp + (size_t)bh * 16 * TILE_U4;
    const uint4* gV = g_Vp + (size_t)bh * 16 * TILE_U4;

    // ---- prefetch tile 0 into stage 0 ----
    #pragma unroll
    for (int i = 0; i < 8; i++) {
        int idx = tid + i * NTHR;
        CPASYNC16(sbase + idx * 16,         gK + idx);
        CPASYNC16(sbase + 16384 + idx * 16, gV + idx);
    }
    CPCOMMIT();

    // ---- Q a-fragments (fp16, register resident) ----
    uint32_t qa[8][4];
    {
        const float* Qp0 = Qg + headoff + (size_t)(q0 + rl0) * DHEAD;
        const float* Qp1 = Qg + headoff + (size_t)(q0 + rl1) * DHEAD;
        #pragma unroll
        for (int ks = 0; ks < 8; ks++) {
            int c = ks * 16 + 2 * t4;
            qa[ks][0] = h2pack(Qp0[c],     Qp0[c + 1]);
            qa[ks][1] = h2pack(Qp1[c],     Qp1[c + 1]);
            qa[ks][2] = h2pack(Qp0[c + 8], Qp0[c + 9]);
            qa[ks][3] = h2pack(Qp1[c + 8], Qp1[c + 9]);
        }
    }

    float oacc[16][4];
    #pragma unroll
    for (int nd = 0; nd < 16; nd++) {
        oacc[nd][0] = 0.f; oacc[nd][1] = 0.f; oacc[nd][2] = 0.f; oacc[nd][3] = 0.f;
    }
    float lsum0 = 0.f, lsum1 = 0.f;

    const uint32_t* mrow0 = g_maskbits + (size_t)(q0 + rl0) * 32;
    const uint32_t* mrow1 = g_maskbits + (size_t)(q0 + rl1) * 32;

    for (int kt = 0; kt < NSEQ / BN; kt++) {
        const int cur = kt & 1;

        // masks for this tile (L2 hits; issued early, consumed after S-mma)
        uint32_t m00 = __ldg(mrow0 + kt * 2), m01 = __ldg(mrow0 + kt * 2 + 1);
        uint32_t m10 = __ldg(mrow1 + kt * 2), m11 = __ldg(mrow1 + kt * 2 + 1);

        __syncthreads();   // all warps finished computing on the spare stage

        // prefetch next tile into the spare stage
        if (kt + 1 < NSEQ / BN) {
            const uint4* nK = gK + (size_t)(kt + 1) * TILE_U4;
            const uint4* nV = gV + (size_t)(kt + 1) * TILE_U4;
            uint32_t dst = sbase + (cur ^ 1) * 32768;
            #pragma unroll
            for (int i = 0; i < 8; i++) {
                int idx = tid + i * NTHR;
                CPASYNC16(dst + idx * 16,         nK + idx);
                CPASYNC16(dst + 16384 + idx * 16, nV + idx);
            }
        }
        CPCOMMIT();
        CPWAIT1();         // current tile has landed (1 group may stay in flight)
        __syncthreads();

        const uint4* sK = smem + cur * 2048;
        const uint4* sV = sK + 1024;

        // ---- two 32-col halves: S -> exp -> PV ----
        #pragma unroll
        for (int h = 0; h < 2; h++) {
            float sacc[4][4];
            #pragma unroll
            for (int nbl = 0; nbl < 4; nbl++) {
                sacc[nbl][0] = 0.f; sacc[nbl][1] = 0.f;
                sacc[nbl][2] = 0.f; sacc[nbl][3] = 0.f;
            }
            #pragma unroll
            for (int kpp = 0; kpp < 4; kpp++) {
                #pragma unroll
                for (int nbl = 0; nbl < 4; nbl++) {
                    int nb = h * 4 + nbl;
                    uint4 kw = sK[(nb * 4 + kpp) * 32 + lane];
                    mma_f16(sacc[nbl], qa[2 * kpp],     kw.x, kw.y);
                    mma_f16(sacc[nbl], qa[2 * kpp + 1], kw.z, kw.w);
                }
            }

            uint32_t mr0 = h ? m01 : m00;
            uint32_t mr1 = h ? m11 : m10;
            uint32_t pa2[2][4];          // a-frags for the 2 PV k-steps of this half
            #pragma unroll
            for (int nbl = 0; nbl < 4; nbl++) {
                int bi = nbl * 8 + 2 * t4;
                // scale already folded into K prepack: exp input is sacc directly
                float p0 = ((mr0 >> bi) & 1u)       ? __expf(sacc[nbl][0]) : 0.f;
                float p1 = ((mr0 >> (bi + 1)) & 1u) ? __expf(sacc[nbl][1]) : 0.f;
                float p2 = ((mr1 >> bi) & 1u)       ? __expf(sacc[nbl][2]) : 0.f;
                float p3 = ((mr1 >> (bi + 1)) & 1u) ? __expf(sacc[nbl][3]) : 0.f;
                lsum0 += p0 + p1;
                lsum1 += p2 + p3;
                // fp16 S c-frag == PV a-frag rows (half2-packed): no shuffles needed
                int j = nbl >> 1;
                if ((nbl & 1) == 0) {
                    pa2[j][0] = h2pack(p0, p1);
                    pa2[j][1] = h2pack(p2, p3);
                } else {
                    pa2[j][2] = h2pack(p0, p1);
                    pa2[j][3] = h2pack(p2, p3);
                }
            }

            #pragma unroll
            for (int j = 0; j < 2; j++) {
                int ks2 = 2 * h + j;
                #pragma unroll
                for (int nd2 = 0; nd2 < 8; nd2++) {
                    uint4 vw = sV[(ks2 * 8 + nd2) * 32 + lane];
                    mma_f16(oacc[2 * nd2],     pa2[j], vw.x, vw.y);
                    mma_f16(oacc[2 * nd2 + 1], pa2[j], vw.z, vw.w);
                }
            }
        }
    }

    // ---- epilogue ----
    lsum0 += __shfl_xor_sync(0xffffffffu, lsum0, 1);
    lsum0 += __shfl_xor_sync(0xffffffffu, lsum0, 2);
    lsum1 += __shfl_xor_sync(0xffffffffu, lsum1, 1);
    lsum1 += __shfl_xor_sync(0xffffffffu, lsum1, 2);
    float inv0 = 1.0f / lsum0;
    float inv1 = 1.0f / lsum1;

    float* o0 = Out + headoff + (size_t)(q0 + rl0) * DHEAD;
    float* o1 = Out + headoff + (size_t)(q0 + rl1) * DHEAD;
    #pragma unroll
    for (int nd = 0; nd < 16; nd++) {
        int c = nd * 8 + 2 * t4;
        float2 a; a.x = oacc[nd][0] * inv0; a.y = oacc[nd][1] * inv0;
        *(float2*)(o0 + c) = a;
        float2 b; b.x = oacc[nd][2] * inv1; b.y = oacc[nd][3] * inv1;
        *(float2*)(o1 + c) = b;
    }
}

extern "C" void kernel_launch(void* const* d_in, const int* in_sizes, int n_in,
                              void* d_out, int out_size) {
    const float* Q   = (const float*)d_in[0];
    const float* K   = (const float*)d_in[1];
    const float* V   = (const float*)d_in[2];
    const int*   adj = (const int*)d_in[3];
    float* out = (float*)d_out;

    const int BH = in_sizes[0] / (NSEQ * DHEAD);     // 64

    prepack_kernel<<<PK_KB + PK_VB + PK_MB, 256>>>(K, V, adj);

    cudaFuncSetAttribute(attn_f16_kernel,
                         cudaFuncAttributeMaxDynamicSharedMemorySize, SMEM_BYTES);

    dim3 grid(NSEQ / BM, BH);
    attn_f16_kernel<<<grid, NTHR, SMEM_BYTES>>>(Q, out);
}

// round 12
// speedup vs baseline: 1.2809x; 1.0537x over previous
#include <cuda_runtime.h>
#include <cuda_fp16.h>
#include <cstdint>

#define NSEQ   1024
#define DHEAD  128
#define BM     64
#define BN     64
#define NTHR   128
#define BH_TOT 64
#define TILE_U4 1024          // uint4 per packed tile (16 KB)
#define SMEM_BYTES (4 * TILE_U4 * 16)   // 2 stages x (K|V) = 64 KB

// packed fp16 fragment-ready operands (16 MB each) + adj bitmask
__device__ uint4    g_Kp[BH_TOT * 16 * TILE_U4];
__device__ uint4    g_Vp[BH_TOT * 16 * TILE_U4];
__device__ uint32_t g_maskbits[NSEQ * (NSEQ / 32)];

__device__ __forceinline__ uint32_t h2pack(float a, float b) {
    __half2 h = __floats2half2_rn(a, b);
    return *reinterpret_cast<uint32_t*>(&h);
}

__device__ __forceinline__ void mma_f16(float c[4], const uint32_t a[4],
                                        uint32_t b0, uint32_t b1) {
    asm volatile(
        "mma.sync.aligned.m16n8k16.row.col.f32.f16.f16.f32 "
        "{%0,%1,%2,%3}, {%4,%5,%6,%7}, {%8,%9}, {%0,%1,%2,%3};"
        : "+f"(c[0]), "+f"(c[1]), "+f"(c[2]), "+f"(c[3])
        : "r"(a[0]), "r"(a[1]), "r"(a[2]), "r"(a[3]), "r"(b0), "r"(b1));
}

#define CPASYNC16(dst, src) \
    asm volatile("cp.async.cg.shared.global [%0], [%1], 16;" :: "r"(dst), "l"(src))
#define CPCOMMIT() asm volatile("cp.async.commit_group;")
#define CPWAIT1()  asm volatile("cp.async.wait_group 1;" ::: "memory")

// ===== single fused prepass kernel =====
// blocks [0, KB)      : K fragment pack (no scale folding — R8 semantics)
// blocks [KB, KB+VB)  : V fragment pack
// blocks [KB+VB, +MB) : adj bitmask pack
#define PK_KB 4096
#define PK_VB 4096
#define PK_MB 128
__global__ void prepack_kernel(const float* __restrict__ K,
                               const float* __restrict__ V,
                               const int*   __restrict__ adj) {
    int b = blockIdx.x;
    if (b < PK_KB) {
        int t = b * 256 + threadIdx.x;                 // 0..1048575
        int lane = t & 31;
        int g = lane >> 2, t4 = lane & 3;
        int kpp = (t >> 5) & 3, nb = (t >> 7) & 7;
        int kt = (t >> 10) & 15, bh = t >> 14;
        const float* src = K + ((size_t)bh * NSEQ + kt * 64 + nb * 8 + g) * DHEAD
                             + 32 * kpp + 2 * t4;
        uint4 o;
        o.x = h2pack(src[0],  src[1]);
        o.y = h2pack(src[8],  src[9]);
        o.z = h2pack(src[16], src[17]);
        o.w = h2pack(src[24], src[25]);
        g_Kp[t] = o;
    } else if (b < PK_KB + PK_VB) {
        int t = (b - PK_KB) * 256 + threadIdx.x;
        int lane = t & 31;
        int g = lane >> 2, t4 = lane & 3;
        int nd2 = (t >> 5) & 7, ks2 = (t >> 8) & 3;
        int kt = (t >> 10) & 15, bh = t >> 14;
        int ra = kt * 64 + 16 * ks2 + 2 * t4;
        int c0 = 16 * nd2 + g;
        const float* src = V + ((size_t)bh * NSEQ + ra) * DHEAD;
        uint4 o;
        o.x = h2pack(src[c0],                 src[DHEAD + c0]);
        o.y = h2pack(src[8 * DHEAD + c0],     src[9 * DHEAD + c0]);
        o.z = h2pack(src[c0 + 8],             src[DHEAD + c0 + 8]);
        o.w = h2pack(src[8 * DHEAD + c0 + 8], src[9 * DHEAD + c0 + 8]);
        g_Vp[t] = o;
    } else {
        int idx = (b - PK_KB - PK_VB) * 256 + threadIdx.x;   // 0..32767
        const int4* src = (const int4*)(adj + (size_t)idx * 32);
        uint32_t m = 0;
        #pragma unroll
        for (int i = 0; i < 8; i++) {
            int4 v = src[i];
            m |= (v.x > 0 ? 1u : 0u) << (4 * i);
            m |= (v.y > 0 ? 1u : 0u) << (4 * i + 1);
            m |= (v.z > 0 ? 1u : 0u) << (4 * i + 2);
            m |= (v.w > 0 ? 1u : 0u) << (4 * i + 3);
        }
        g_maskbits[idx] = m;
    }
}

// ===== main kernel: exact R8 structure (BM=64, 4 warps, 2-stage pipeline) =====
__global__ __launch_bounds__(NTHR, 3)
void attn_f16_kernel(const float* __restrict__ Qg, float* __restrict__ Out) {
    extern __shared__ uint4 smem[];                      // [2][2048]: stage -> K(1024)|V(1024)
    const uint32_t sbase = (uint32_t)__cvta_generic_to_shared(smem);

    const int tid  = threadIdx.x;
    const int w    = tid >> 5;
    const int lane = tid & 31;
    const int g    = lane >> 2;
    const int t4   = lane & 3;
    const int bh   = blockIdx.y;
    const int q0   = blockIdx.x * BM;
    const int rl0  = w * 16 + g;
    const int rl1  = rl0 + 8;
    const size_t headoff = (size_t)bh * NSEQ * DHEAD;

    const uint4* gK = g_Kp + (size_t)bh * 16 * TILE_U4;
    const uint4* gV = g_Vp + (size_t)bh * 16 * TILE_U4;

    // ---- prefetch tile 0 into stage 0 ----
    #pragma unroll
    for (int i = 0; i < 8; i++) {
        int idx = tid + i * NTHR;
        CPASYNC16(sbase + idx * 16,         gK + idx);
        CPASYNC16(sbase + 16384 + idx * 16, gV + idx);
    }
    CPCOMMIT();

    // ---- Q a-fragments (fp16, register resident) ----
    uint32_t qa[8][4];
    {
        const float* Qp0 = Qg + headoff + (size_t)(q0 + rl0) * DHEAD;
        const float* Qp1 = Qg + headoff + (size_t)(q0 + rl1) * DHEAD;
        #pragma unroll
        for (int ks = 0; ks < 8; ks++) {
            int c = ks * 16 + 2 * t4;
            qa[ks][0] = h2pack(Qp0[c],     Qp0[c + 1]);
            qa[ks][1] = h2pack(Qp1[c],     Qp1[c + 1]);
            qa[ks][2] = h2pack(Qp0[c + 8], Qp0[c + 9]);
            qa[ks][3] = h2pack(Qp1[c + 8], Qp1[c + 9]);
        }
    }

    float oacc[16][4];
    #pragma unroll
    for (int nd = 0; nd < 16; nd++) {
        oacc[nd][0] = 0.f; oacc[nd][1] = 0.f; oacc[nd][2] = 0.f; oacc[nd][3] = 0.f;
    }
    float lsum0 = 0.f, lsum1 = 0.f;

    const uint32_t* mrow0 = g_maskbits + (size_t)(q0 + rl0) * 32;
    const uint32_t* mrow1 = g_maskbits + (size_t)(q0 + rl1) * 32;

    for (int kt = 0; kt < NSEQ / BN; kt++) {
        const int cur = kt & 1;

        // masks for this tile (L2 hits; issued early, consumed after S-mma)
        uint32_t m00 = mrow0[kt * 2], m01 = mrow0[kt * 2 + 1];
        uint32_t m10 = mrow1[kt * 2], m11 = mrow1[kt * 2 + 1];

        __syncthreads();   // all warps finished computing on the spare stage

        // prefetch next tile into the spare stage
        if (kt + 1 < NSEQ / BN) {
            const uint4* nK = gK + (size_t)(kt + 1) * TILE_U4;
            const uint4* nV = gV + (size_t)(kt + 1) * TILE_U4;
            uint32_t dst = sbase + (cur ^ 1) * 32768;
            #pragma unroll
            for (int i = 0; i < 8; i++) {
                int idx = tid + i * NTHR;
                CPASYNC16(dst + idx * 16,         nK + idx);
                CPASYNC16(dst + 16384 + idx * 16, nV + idx);
            }
        }
        CPCOMMIT();
        CPWAIT1();         // current tile has landed (1 group may stay in flight)
        __syncthreads();

        const uint4* sK = smem + cur * 2048;
        const uint4* sV = sK + 1024;

        // ---- two 32-col halves: S -> exp -> PV ----
        #pragma unroll
        for (int h = 0; h < 2; h++) {
            float sacc[4][4];
            #pragma unroll
            for (int nbl = 0; nbl < 4; nbl++) {
                sacc[nbl][0] = 0.f; sacc[nbl][1] = 0.f;
                sacc[nbl][2] = 0.f; sacc[nbl][3] = 0.f;
            }
            #pragma unroll
            for (int kpp = 0; kpp < 4; kpp++) {
                #pragma unroll
                for (int nbl = 0; nbl < 4; nbl++) {
                    int nb = h * 4 + nbl;
                    uint4 kw = sK[(nb * 4 + kpp) * 32 + lane];
                    mma_f16(sacc[nbl], qa[2 * kpp],     kw.x, kw.y);
                    mma_f16(sacc[nbl], qa[2 * kpp + 1], kw.z, kw.w);
                }
            }

            uint32_t mr0 = h ? m01 : m00;
            uint32_t mr1 = h ? m11 : m10;
            uint32_t pa2[2][4];          // a-frags for the 2 PV k-steps of this half
            #pragma unroll
            for (int nbl = 0; nbl < 4; nbl++) {
                int bi = nbl * 8 + 2 * t4;
                float p0 = ((mr0 >> bi) & 1u)       ? __expf(sacc[nbl][0] * 0.125f) : 0.f;
                float p1 = ((mr0 >> (bi + 1)) & 1u) ? __expf(sacc[nbl][1] * 0.125f) : 0.f;
                float p2 = ((mr1 >> bi) & 1u)       ? __expf(sacc[nbl][2] * 0.125f) : 0.f;
                float p3 = ((mr1 >> (bi + 1)) & 1u) ? __expf(sacc[nbl][3] * 0.125f) : 0.f;
                lsum0 += p0 + p1;
                lsum1 += p2 + p3;
                // fp16 S c-frag == PV a-frag rows (half2-packed): no shuffles needed
                int j = nbl >> 1;
                if ((nbl & 1) == 0) {
                    pa2[j][0] = h2pack(p0, p1);
                    pa2[j][1] = h2pack(p2, p3);
                } else {
                    pa2[j][2] = h2pack(p0, p1);
                    pa2[j][3] = h2pack(p2, p3);
                }
            }

            #pragma unroll
            for (int j = 0; j < 2; j++) {
                int ks2 = 2 * h + j;
                #pragma unroll
                for (int nd2 = 0; nd2 < 8; nd2++) {
                    uint4 vw = sV[(ks2 * 8 + nd2) * 32 + lane];
                    mma_f16(oacc[2 * nd2],     pa2[j], vw.x, vw.y);
                    mma_f16(oacc[2 * nd2 + 1], pa2[j], vw.z, vw.w);
                }
            }
        }
    }

    // ---- epilogue ----
    lsum0 += __shfl_xor_sync(0xffffffffu, lsum0, 1);
    lsum0 += __shfl_xor_sync(0xffffffffu, lsum0, 2);
    lsum1 += __shfl_xor_sync(0xffffffffu, lsum1, 1);
    lsum1 += __shfl_xor_sync(0xffffffffu, lsum1, 2);
    float inv0 = 1.0f / lsum0;
    float inv1 = 1.0f / lsum1;

    float* o0 = Out + headoff + (size_t)(q0 + rl0) * DHEAD;
    float* o1 = Out + headoff + (size_t)(q0 + rl1) * DHEAD;
    #pragma unroll
    for (int nd = 0; nd < 16; nd++) {
        int c = nd * 8 + 2 * t4;
        float2 a; a.x = oacc[nd][0] * inv0; a.y = oacc[nd][1] * inv0;
        *(float2*)(o0 + c) = a;
        float2 b; b.x = oacc[nd][2] * inv1; b.y = oacc[nd][3] * inv1;
        *(float2*)(o1 + c) = b;
    }
}

extern "C" void kernel_launch(void* const* d_in, const int* in_sizes, int n_in,
                              void* d_out, int out_size) {
    const float* Q   = (const float*)d_in[0];
    const float* K   = (const float*)d_in[1];
    const float* V   = (const float*)d_in[2];
    const int*   adj = (const int*)d_in[3];
    float* out = (float*)d_out;

    const int BH = in_sizes[0] / (NSEQ * DHEAD);     // 64

    prepack_kernel<<<PK_KB + PK_VB + PK_MB, 256>>>(K, V, adj);

    cudaFuncSetAttribute(attn_f16_kernel,
                         cudaFuncAttributeMaxDynamicSharedMemorySize, SMEM_BYTES);

    dim3 grid(NSEQ / BM, BH);
    attn_f16_kernel<<<grid, NTHR, SMEM_BYTES>>>(Q, out);
}